// round 2
// baseline (speedup 1.0000x reference)
#include <cuda_runtime.h>
#include <math.h>

// Problem shape (fixed for this bench)
#define T_STEPS 64
#define BATCH   1024
#define HID     512
#define VOCAB   512
#define G4H     2048   // 4*HID

// ---------------- scratch state (allocation-free: __device__ globals) --------
__device__ __align__(16) float g_x[BATCH * HID];      // current input embedding
__device__ __align__(16) float g_h[BATCH * HID];      // hidden state
__device__ __align__(16) float g_c[BATCH * HID];      // cell state
__device__ __align__(16) float g_gates[BATCH * G4H];  // pre-activation gates

// ---------------- init: x = embedding[SOS=0], h = enc_h, c = enc_c ----------
__global__ void init_state(const float* __restrict__ emb,
                           const float* __restrict__ enc_h,
                           const float* __restrict__ enc_c)
{
    int idx = blockIdx.x * blockDim.x + threadIdx.x;   // [0, BATCH*HID)
    int j = idx & (HID - 1);
    g_x[idx] = emb[j];          // SOS row 0
    g_h[idx] = enc_h[idx];
    g_c[idx] = enc_c[idx];
}

// ---------------- gates GEMM: gates = x@W_ih^T + h@W_hh^T + (b_ih+b_hh) -----
// M=1024, N=2048, K=512 (twice). Tiles 128x128x16, 256 threads, 8x8 microtile.
__global__ __launch_bounds__(256, 2)
void gates_gemm(const float* __restrict__ W_ih, const float* __restrict__ W_hh,
                const float* __restrict__ b_ih, const float* __restrict__ b_hh)
{
    const int BM = 128, BN = 128, BK = 16;
    __shared__ float As[BK][BM];
    __shared__ float Bs[BK][BN];

    int tid = threadIdx.x;
    int tx = tid & 15;          // 0..15 -> N
    int ty = tid >> 4;          // 0..15 -> M
    int m0 = blockIdx.y * BM;
    int n0 = blockIdx.x * BN;

    float acc[8][8];
#pragma unroll
    for (int i = 0; i < 8; i++)
#pragma unroll
        for (int j = 0; j < 8; j++) acc[i][j] = 0.f;

#pragma unroll 1
    for (int half = 0; half < 2; half++) {
        const float* A = half ? g_h : g_x;             // [1024, 512]
        const float* W = half ? W_hh : W_ih;           // [2048, 512]
#pragma unroll 1
        for (int k0 = 0; k0 < HID; k0 += BK) {
            // load 128x16 tiles of A and W (transposed into smem)
#pragma unroll
            for (int i = 0; i < 2; i++) {
                int lid = tid + i * 256;               // 0..511
                int row = lid >> 2;                    // 0..127
                int cv  = (lid & 3) * 4;               // 0,4,8,12
                float4 va = *(const float4*)&A[(size_t)(m0 + row) * HID + k0 + cv];
                As[cv + 0][row] = va.x; As[cv + 1][row] = va.y;
                As[cv + 2][row] = va.z; As[cv + 3][row] = va.w;
                float4 vb = *(const float4*)&W[(size_t)(n0 + row) * HID + k0 + cv];
                Bs[cv + 0][row] = vb.x; Bs[cv + 1][row] = vb.y;
                Bs[cv + 2][row] = vb.z; Bs[cv + 3][row] = vb.w;
            }
            __syncthreads();
#pragma unroll
            for (int k = 0; k < BK; k++) {
                float a[8], b[8];
                *(float4*)&a[0] = *(const float4*)&As[k][ty * 8];
                *(float4*)&a[4] = *(const float4*)&As[k][ty * 8 + 4];
                *(float4*)&b[0] = *(const float4*)&Bs[k][tx * 8];
                *(float4*)&b[4] = *(const float4*)&Bs[k][tx * 8 + 4];
#pragma unroll
                for (int i = 0; i < 8; i++)
#pragma unroll
                    for (int j = 0; j < 8; j++)
                        acc[i][j] = fmaf(a[i], b[j], acc[i][j]);
            }
            __syncthreads();
        }
    }

    // epilogue: add combined bias, store gates
#pragma unroll
    for (int i = 0; i < 8; i++) {
        int m = m0 + ty * 8 + i;
#pragma unroll
        for (int j = 0; j < 8; j++) {
            int n = n0 + tx * 8 + j;
            g_gates[(size_t)m * G4H + n] = acc[i][j] + b_ih[n] + b_hh[n];
        }
    }
}

// ---------------- LSTM cell pointwise ---------------------------------------
__global__ void lstm_cell()
{
    int idx = blockIdx.x * blockDim.x + threadIdx.x;   // [0, BATCH*HID)
    int b = idx >> 9;
    int j = idx & (HID - 1);
    const float* g = g_gates + (size_t)b * G4H;
    float gi = g[j];
    float gf = g[j + 512];
    float gg = g[j + 1024];
    float go = g[j + 1536];
    float i_s = 1.f / (1.f + expf(-gi));
    float f_s = 1.f / (1.f + expf(-gf));
    float o_s = 1.f / (1.f + expf(-go));
    float c = f_s * g_c[idx] + i_s * tanhf(gg);
    g_c[idx] = c;
    g_h[idx] = o_s * tanhf(c);
}

// ---------------- logits GEMM: logits = h@W_out^T + b_out -------------------
// M=1024, N=512, K=512. Tiles 64x64x16, 256 threads, 4x4 microtile.
__global__ __launch_bounds__(256, 4)
void logits_gemm(const float* __restrict__ W_out, const float* __restrict__ b_out,
                 float* __restrict__ out)
{
    const int BM = 64, BN = 64, BK = 16;
    __shared__ float As[BK][BM];
    __shared__ float Bs[BK][BN];

    int tid = threadIdx.x;
    int tx = tid & 15;
    int ty = tid >> 4;
    int m0 = blockIdx.y * BM;
    int n0 = blockIdx.x * BN;

    float acc[4][4];
#pragma unroll
    for (int i = 0; i < 4; i++)
#pragma unroll
        for (int j = 0; j < 4; j++) acc[i][j] = 0.f;

    int row = tid >> 2;                 // 0..63
    int cv  = (tid & 3) * 4;            // 0,4,8,12

#pragma unroll 1
    for (int k0 = 0; k0 < HID; k0 += BK) {
        float4 va = *(const float4*)&g_h[(size_t)(m0 + row) * HID + k0 + cv];
        As[cv + 0][row] = va.x; As[cv + 1][row] = va.y;
        As[cv + 2][row] = va.z; As[cv + 3][row] = va.w;
        float4 vb = *(const float4*)&W_out[(size_t)(n0 + row) * HID + k0 + cv];
        Bs[cv + 0][row] = vb.x; Bs[cv + 1][row] = vb.y;
        Bs[cv + 2][row] = vb.z; Bs[cv + 3][row] = vb.w;
        __syncthreads();
#pragma unroll
        for (int k = 0; k < BK; k++) {
            float a[4], b[4];
            *(float4*)&a[0] = *(const float4*)&As[k][ty * 4];
            *(float4*)&b[0] = *(const float4*)&Bs[k][tx * 4];
#pragma unroll
            for (int i = 0; i < 4; i++)
#pragma unroll
                for (int j = 0; j < 4; j++)
                    acc[i][j] = fmaf(a[i], b[j], acc[i][j]);
        }
        __syncthreads();
    }

#pragma unroll
    for (int i = 0; i < 4; i++) {
        int m = m0 + ty * 4 + i;
#pragma unroll
        for (int j = 0; j < 4; j++) {
            int n = n0 + tx * 4 + j;
            out[(size_t)m * VOCAB + n] = acc[i][j] + b_out[n];
        }
    }
}

// ---------------- argmax over V + embedding gather --------------------------
// one block (128 threads) per batch row; first-max tie-break to match jnp.argmax
__global__ void argmax_gather(const float* __restrict__ logits,
                              const float* __restrict__ emb)
{
    int b = blockIdx.x;
    const float* row = logits + (size_t)b * VOCAB;
    int tid = threadIdx.x;

    float best = -INFINITY;
    int bi = 0;
#pragma unroll
    for (int m = 0; m < VOCAB / 128; m++) {
        int j = tid + m * 128;
        float v = row[j];
        if (v > best) { best = v; bi = j; }   // strict > keeps earliest index
    }
    // warp reduce (prefer lower index on exact ties)
#pragma unroll
    for (int off = 16; off; off >>= 1) {
        float ov = __shfl_down_sync(0xffffffffu, best, off);
        int   oi = __shfl_down_sync(0xffffffffu, bi, off);
        if (ov > best || (ov == best && oi < bi)) { best = ov; bi = oi; }
    }
    __shared__ float sv[4];
    __shared__ int   si[4];
    __shared__ int   s_idx;
    if ((tid & 31) == 0) { sv[tid >> 5] = best; si[tid >> 5] = bi; }
    __syncthreads();
    if (tid == 0) {
        float bv = sv[0]; int bb = si[0];
#pragma unroll
        for (int w = 1; w < 4; w++)
            if (sv[w] > bv || (sv[w] == bv && si[w] < bb)) { bv = sv[w]; bb = si[w]; }
        s_idx = bb;
    }
    __syncthreads();
    int idx = s_idx;
    // gather next input embedding: 512 floats = 128 float4
    const float4* src = (const float4*)(emb + (size_t)idx * HID);
    float4* dst = (float4*)(g_x + (size_t)b * HID);
    dst[tid] = src[tid];
}

// ---------------- launch ----------------------------------------------------
extern "C" void kernel_launch(void* const* d_in, const int* in_sizes, int n_in,
                              void* d_out, int out_size)
{
    // metadata order:
    // 0 target_var(i64), 1 target_max_len, 2 encoder_hidden, 3 encoder_cell,
    // 4 embedding, 5 W_ih, 6 W_hh, 7 b_ih, 8 b_hh, 9 W_out, 10 b_out
    const float* enc_h = (const float*)d_in[2];
    const float* enc_c = (const float*)d_in[3];
    const float* emb   = (const float*)d_in[4];
    const float* W_ih  = (const float*)d_in[5];
    const float* W_hh  = (const float*)d_in[6];
    const float* b_ih  = (const float*)d_in[7];
    const float* b_hh  = (const float*)d_in[8];
    const float* W_out = (const float*)d_in[9];
    const float* b_out = (const float*)d_in[10];
    float* out = (float*)d_out;

    init_state<<<(BATCH * HID) / 256, 256>>>(emb, enc_h, enc_c);

    for (int t = 0; t < T_STEPS; t++) {
        gates_gemm<<<dim3(G4H / 128, BATCH / 128), 256>>>(W_ih, W_hh, b_ih, b_hh);
        lstm_cell<<<(BATCH * HID) / 256, 256>>>();
        float* logits_t = out + (size_t)t * BATCH * VOCAB;
        logits_gemm<<<dim3(VOCAB / 64, BATCH / 64), 256>>>(W_out, b_out, logits_t);
        argmax_gather<<<BATCH, 128>>>(logits_t, emb);
    }
}